// round 13
// baseline (speedup 1.0000x reference)
#include <cuda_runtime.h>
#include <cstdint>

#define NN 100096
#define FF 64
#define EB 128   // edges per scatter block

// ---------------- scratch (device globals: no runtime allocation) ----------
__device__ float g_sum_pos[(size_t)NN * FF];
__device__ float g_sum_neg[(size_t)NN * FF];
__device__ float g_cnt_pos[NN];
__device__ float g_cnt_neg[NN];

__device__ __forceinline__ float wsum(float v) {
#pragma unroll
    for (int o = 16; o > 0; o >>= 1) v += __shfl_xor_sync(0xffffffffu, v, o);
    return v;
}

// packed f32x2 helpers (sm_103a)
__device__ __forceinline__ unsigned long long fma2(unsigned long long a,
                                                   unsigned long long b,
                                                   unsigned long long c) {
    unsigned long long d;
    asm("fma.rn.f32x2 %0, %1, %2, %3;" : "=l"(d) : "l"(a), "l"(b), "l"(c));
    return d;
}
__device__ __forceinline__ unsigned long long pack2(float v) {
    unsigned long long d;
    asm("mov.b64 %0, {%1, %1};" : "=l"(d) : "r"(__float_as_uint(v)));
    return d;
}
__device__ __forceinline__ float2 unpack2(unsigned long long a) {
    unsigned int lo, hi;
    asm("mov.b64 {%0, %1}, %2;" : "=r"(lo), "=r"(hi) : "l"(a));
    return make_float2(__uint_as_float(lo), __uint_as_float(hi));
}

// ---------------- scatter: smem-staged indices, 16 threads/edge ------------
__global__ void scatter_kernel(const float* __restrict__ x,
                               const int* __restrict__ pei, const int* __restrict__ nei,
                               float* __restrict__ sp, float* __restrict__ sn,
                               float* __restrict__ cp, float* __restrict__ cn, int E) {
    __shared__ int s_src[EB], s_dst[EB];
    const int* ei = blockIdx.y ? nei : pei;
    float* sum = blockIdx.y ? sn : sp;
    float* cnt = blockIdx.y ? cn : cp;
    long base = (long)blockIdx.x * EB;
    int tid = threadIdx.x;
    if (tid < EB) {
        long e = base + tid;
        s_src[tid] = (e < E) ? ei[e] : -1;
    } else {
        long e = base + (tid - EB);
        s_dst[tid - EB] = (e < E) ? ei[(long)E + e] : -1;
    }
    __syncthreads();
    int ch = tid & 15, eg = tid >> 4;
#pragma unroll
    for (int it = 0; it < EB / 16; ++it) {
        int e = it * 16 + eg;
        int dst = s_dst[e];
        if (dst < 0) continue;
        int src = s_src[e];
        float4 v = *reinterpret_cast<const float4*>(x + (size_t)src * FF + ch * 4);
        float* a = sum + (size_t)dst * FF + ch * 4;
        asm volatile("red.global.add.v4.f32 [%0], {%1,%2,%3,%4};"
                     :: "l"(a), "f"(v.x), "f"(v.y), "f"(v.z), "f"(v.w) : "memory");
        if (ch == 0)
            asm volatile("red.global.add.f32 [%0], %1;" :: "l"(cnt + dst), "f"(1.0f) : "memory");
    }
}

// ---------------- fused GEMM + hyperbolic epilogue -------------------------
// block: 64 nodes x one branch (by=0 pos, by=1 neg); both matrices of the
// branch; bias computed in-block; writes out[node][by*64 : +64] directly.
// thread: og=tid&7 (8 outputs), ng=tid>>3 (2 nodes: 2*ng, 2*ng+1)
__global__ void __launch_bounds__(256, 3)
fused_kernel(const float* __restrict__ x,
             const float* __restrict__ Wp,  const float* __restrict__ Wpc,
             const float* __restrict__ Wn,  const float* __restrict__ Wnc,
             const float* __restrict__ bpc, const float* __restrict__ bnc,
             float* __restrict__ out, int n) {
    extern __shared__ float sh[];
    float* sAa = sh;                    // [64][64] mean vectors (scaled)
    float* sAx = sh + 64 * 64;          // [64][64] x vectors
    float* sWa = sh + 2 * 64 * 64;      // [64][68] W_agg transposed
    float* sWc = sWa + 64 * 68;         // [64][68] W_cc transposed
    float* sPN = sWc + 64 * 68;         // [64] ||mean|| clipped
    float* sXN = sPN + 64;              // [64] ||x||    clipped
    float* sHB = sXN + 64;              // [65] hyp bias + y2

    int by = blockIdx.y;
    const float* Wagg = by ? Wn : Wp;
    const float* Wcc  = by ? Wnc : Wpc;
    const float* sums = by ? g_sum_neg : g_sum_pos;
    const float* cnts = by ? g_cnt_neg : g_cnt_pos;
    long node0 = (long)blockIdx.x * 64;
    int tid = threadIdx.x;

    // warp 0: hyperbolic bias proj(expmap0(b)) for this branch
    if (tid < 32) {
        const float* b = by ? bnc : bpc;
        float u0 = b[tid], u1 = b[tid + 32];
        float nb = fmaxf(sqrtf(wsum(u0 * u0 + u1 * u1)), 1e-15f);
        float s = tanhf(nb) / nb;
        float v0 = u0 * s, v1 = u1 * s;
        float vn = fmaxf(sqrtf(wsum(v0 * v0 + v1 * v1)), 1e-15f);
        if (vn > 0.996f) { float p = 0.996f / vn; v0 *= p; v1 *= p; }
        sHB[tid] = v0; sHB[tid + 32] = v1;
        float y2 = wsum(v0 * v0 + v1 * v1);
        if (tid == 0) sHB[64] = y2;
    }

    // stage weights transposed: sW[k*68+o] = W[o*64+k]
#pragma unroll
    for (int p = 0; p < 16; ++p) {
        int idx = p * 256 + tid;
        int o = idx >> 6, k = idx & 63;
        sWa[k * 68 + o] = Wagg[o * 64 + k];
        sWc[k * 68 + o] = Wcc[o * 64 + k];
    }
    // stage inputs transposed (mean scaling folded in)
    {
        int nl = tid & 63, kc = tid >> 6;   // kc in 0..3
        long gn = node0 + nl;
        bool ok = gn < n;
        long gc = ok ? gn : 0;
        float scale = 1.0f / fmaxf(cnts[gc], 1.0f);
        const float4* rowA = reinterpret_cast<const float4*>(sums + (size_t)gc * 64);
        const float4* rowX = reinterpret_cast<const float4*>(x + (size_t)gc * 64);
#pragma unroll
        for (int pk = 0; pk < 4; ++pk) {
            int k4 = kc + 4 * pk;
            float4 va = ok ? rowA[k4] : make_float4(0.f, 0.f, 0.f, 0.f);
            float4 vx = ok ? rowX[k4] : make_float4(0.f, 0.f, 0.f, 0.f);
            sAa[(4 * k4 + 0) * 64 + nl] = va.x * scale;
            sAa[(4 * k4 + 1) * 64 + nl] = va.y * scale;
            sAa[(4 * k4 + 2) * 64 + nl] = va.z * scale;
            sAa[(4 * k4 + 3) * 64 + nl] = va.w * scale;
            sAx[(4 * k4 + 0) * 64 + nl] = vx.x;
            sAx[(4 * k4 + 1) * 64 + nl] = vx.y;
            sAx[(4 * k4 + 2) * 64 + nl] = vx.z;
            sAx[(4 * k4 + 3) * 64 + nl] = vx.w;
        }
    }
    __syncthreads();

    // input norms (clipped): threads 0-63 -> xn, 64-127 -> pn
    if (tid < 128) {
        int nl = tid & 63;
        const float* src = (tid < 64) ? sAx : sAa;
        float acc = 0.f;
#pragma unroll
        for (int k = 0; k < 64; ++k) { float v = src[k * 64 + nl]; acc = fmaf(v, v, acc); }
        float* dst = (tid < 64) ? sXN : sPN;
        dst[nl] = fmaxf(sqrtf(acc), 1e-15f);
    }
    __syncthreads();

    int og = tid & 7, ng = tid >> 3;   // ng 0..31
    float hbv[8];
#pragma unroll
    for (int j = 0; j < 8; ++j) hbv[j] = sHB[8 * og + j];
    float y2 = sHB[64];

    unsigned long long accP[2][4], accC[2][4];
#pragma unroll
    for (int i = 0; i < 2; ++i)
#pragma unroll
        for (int j = 0; j < 4; ++j) { accP[i][j] = 0ull; accC[i][j] = 0ull; }

#pragma unroll 4
    for (int k = 0; k < 64; ++k) {
        float2 aa = *reinterpret_cast<const float2*>(&sAa[k * 64 + 2 * ng]);
        float2 ax = *reinterpret_cast<const float2*>(&sAx[k * 64 + 2 * ng]);
        ulonglong2 wa0 = *reinterpret_cast<const ulonglong2*>(&sWa[k * 68 + 8 * og]);
        ulonglong2 wa1 = *reinterpret_cast<const ulonglong2*>(&sWa[k * 68 + 8 * og + 4]);
        ulonglong2 wc0 = *reinterpret_cast<const ulonglong2*>(&sWc[k * 68 + 8 * og]);
        ulonglong2 wc1 = *reinterpret_cast<const ulonglong2*>(&sWc[k * 68 + 8 * og + 4]);
        float av[2] = {aa.x, aa.y};
        float xv[2] = {ax.x, ax.y};
#pragma unroll
        for (int i = 0; i < 2; ++i) {
            unsigned long long pa = pack2(av[i]);
            unsigned long long px = pack2(xv[i]);
            accP[i][0] = fma2(pa, wa0.x, accP[i][0]);
            accP[i][1] = fma2(pa, wa0.y, accP[i][1]);
            accP[i][2] = fma2(pa, wa1.x, accP[i][2]);
            accP[i][3] = fma2(pa, wa1.y, accP[i][3]);
            accC[i][0] = fma2(px, wc0.x, accC[i][0]);
            accC[i][1] = fma2(px, wc0.y, accC[i][1]);
            accC[i][2] = fma2(px, wc1.x, accC[i][2]);
            accC[i][3] = fma2(px, wc1.y, accC[i][3]);
        }
    }

    // in-register hyperbolic epilogue, one node at a time
#pragma unroll
    for (int i = 0; i < 2; ++i) {
        int node = 2 * ng + i;
        long gn = node0 + node;

        float mvP[8], mvC[8];
#pragma unroll
        for (int j = 0; j < 4; ++j) {
            float2 p = unpack2(accP[i][j]);
            float2 c = unpack2(accC[i][j]);
            mvP[2 * j] = p.x; mvP[2 * j + 1] = p.y;
            mvC[2 * j] = c.x; mvC[2 * j + 1] = c.y;
        }
        float ssP = 0.f, ssC = 0.f, dh = 0.f;
#pragma unroll
        for (int j = 0; j < 8; ++j) {
            ssP = fmaf(mvP[j], mvP[j], ssP);
            ssC = fmaf(mvC[j], mvC[j], ssC);
            dh  = fmaf(mvC[j], hbv[j], dh);
        }
        // reduce across the 8 og-lanes (lane bits 0..2)
#pragma unroll
        for (int o = 1; o < 8; o <<= 1) {
            ssP += __shfl_xor_sync(0xffffffffu, ssP, o);
            ssC += __shfl_xor_sync(0xffffffffu, ssC, o);
            dh  += __shfl_xor_sync(0xffffffffu, dh, o);
        }

        float pn = sPN[node], xn = sXN[node];
        float mnP = fmaxf(sqrtf(ssP), 1e-15f);
        float tP = tanhf(mnP / pn * atanhf(fminf(pn, 1.0f - 1e-7f)));
        float scP = fminf(tP, 0.996f) / mnP;

        float mnC = fmaxf(sqrtf(ssC), 1e-15f);
        float tC = tanhf(mnC / xn * atanhf(fminf(xn, 1.0f - 1e-7f)));
        float sn_ = fminf(tC, 0.996f);
        float scC = sn_ / mnC;

        float xy = scC * dh;
        float x2 = sn_ * sn_;
        float f1 = 1.0f + 2.0f * xy + y2;
        float f2 = 1.0f - x2;
        float den = fmaxf(1.0f + 2.0f * xy + x2 * y2, 1e-15f);
        float inv = 1.0f / den;
        float qsq = fmaxf(f1 * f1 * x2 + 2.0f * f1 * f2 * xy + f2 * f2 * y2, 0.0f) * (inv * inv);
        float qn = fmaxf(sqrtf(qsq), 1e-15f);
        float clip = (qn > 0.996f) ? (0.996f / qn) : 1.0f;
        float g1 = f1 * inv * clip;     // applied to s = mvC*scC
        float g2 = f2 * inv * clip;     // applied to hb

        if (gn < n) {
            float o8[8];
#pragma unroll
            for (int j = 0; j < 8; ++j)
                o8[j] = fmaf(mvP[j], scP, fmaf(mvC[j] * scC, g1, g2 * hbv[j]));
            float4* dst = reinterpret_cast<float4*>(out + gn * 128 + by * 64 + 8 * og);
            dst[0] = make_float4(o8[0], o8[1], o8[2], o8[3]);
            dst[1] = make_float4(o8[4], o8[5], o8[6], o8[7]);
        }
    }
}

// ---------------------------------------------------------------------------
extern "C" void kernel_launch(void* const* d_in, const int* in_sizes, int n_in,
                              void* d_out, int out_size) {
    const float* x   = (const float*)d_in[0];
    const float* Wp  = (const float*)d_in[1];
    const float* Wpc = (const float*)d_in[2];
    const float* bpc = (const float*)d_in[3];
    const float* Wn  = (const float*)d_in[4];
    const float* Wnc = (const float*)d_in[5];
    const float* bnc = (const float*)d_in[6];
    const int* pei   = (const int*)d_in[7];
    const int* nei   = (const int*)d_in[8];
    float* out = (float*)d_out;

    int n = in_sizes[0] / 64;
    int E = in_sizes[7] / 2;

    void *psum_p, *psum_n, *pcnt_p, *pcnt_n;
    cudaGetSymbolAddress(&psum_p, g_sum_pos);
    cudaGetSymbolAddress(&psum_n, g_sum_neg);
    cudaGetSymbolAddress(&pcnt_p, g_cnt_pos);
    cudaGetSymbolAddress(&pcnt_n, g_cnt_neg);
    cudaMemsetAsync(psum_p, 0, (size_t)n * 64 * sizeof(float));
    cudaMemsetAsync(psum_n, 0, (size_t)n * 64 * sizeof(float));
    cudaMemsetAsync(pcnt_p, 0, (size_t)n * sizeof(float));
    cudaMemsetAsync(pcnt_n, 0, (size_t)n * sizeof(float));

    dim3 sgrid((E + EB - 1) / EB, 2);
    scatter_kernel<<<sgrid, 256>>>(x, pei, nei,
                                   (float*)psum_p, (float*)psum_n,
                                   (float*)pcnt_p, (float*)pcnt_n, E);

    // smem: 2*[64x64] + 2*[64x68] + 2*64 + 65 floats = 68,356 B (3 blocks/SM)
    const int FSMEM = (2 * 64 * 64 + 2 * 64 * 68 + 2 * 64 + 65) * (int)sizeof(float);
    cudaFuncSetAttribute(fused_kernel, cudaFuncAttributeMaxDynamicSharedMemorySize, FSMEM);
    dim3 fgrid((n + 63) / 64, 2);
    fused_kernel<<<fgrid, 256, FSMEM>>>(x, Wp, Wpc, Wn, Wnc, bpc, bnc, out, n);
}

// round 14
// speedup vs baseline: 1.1797x; 1.1797x over previous
#include <cuda_runtime.h>
#include <cstdint>

#define NN 100096
#define FF 64
#define EB 128   // edges per scatter block

typedef unsigned long long u64;

// ---------------- scratch (device globals: no runtime allocation) ----------
__device__ float g_sum_pos[(size_t)NN * FF];
__device__ float g_sum_neg[(size_t)NN * FF];
__device__ float g_cnt_pos[NN];
__device__ float g_cnt_neg[NN];
__device__ u64   g_s[(size_t)NN * 64];     // scaled cc-matvec pairs: [(pair*2+by)*64 + o]
__device__ float2 g_meta[(size_t)NN * 2];  // (x2, xy) per [node*2 + by]

__device__ __forceinline__ float wsum(float v) {
#pragma unroll
    for (int o = 16; o > 0; o >>= 1) v += __shfl_xor_sync(0xffffffffu, v, o);
    return v;
}

// packed f32x2 helpers (sm_103a)
__device__ __forceinline__ u64 fma2(u64 a, u64 b, u64 c) {
    u64 d; asm("fma.rn.f32x2 %0, %1, %2, %3;" : "=l"(d) : "l"(a), "l"(b), "l"(c)); return d;
}
__device__ __forceinline__ u64 mul2(u64 a, u64 b) {
    u64 d; asm("mul.rn.f32x2 %0, %1, %2;" : "=l"(d) : "l"(a), "l"(b)); return d;
}
__device__ __forceinline__ u64 add2(u64 a, u64 b) {
    u64 d; asm("add.rn.f32x2 %0, %1, %2;" : "=l"(d) : "l"(a), "l"(b)); return d;
}
__device__ __forceinline__ u64 pack2(float v) {
    u64 d; asm("mov.b64 %0, {%1, %1};" : "=l"(d) : "r"(__float_as_uint(v))); return d;
}
__device__ __forceinline__ u64 packlh(float lo, float hi) {
    u64 d; asm("mov.b64 %0, {%1, %2};" : "=l"(d) : "r"(__float_as_uint(lo)), "r"(__float_as_uint(hi))); return d;
}
__device__ __forceinline__ float2 unpack2(u64 a) {
    unsigned int lo, hi;
    asm("mov.b64 {%0, %1}, %2;" : "=r"(lo), "=r"(hi) : "l"(a));
    return make_float2(__uint_as_float(lo), __uint_as_float(hi));
}

// smem layout constants (floats): sA [64][256], sWd u64[64][73], norms[256], hb[66]
#define SWD_OFF   (64 * 256)
#define SN_OFF    (SWD_OFF + 64 * 73 * 2)
#define SHB_OFF   (SN_OFF + 256)
#define FSMEM_FLOATS (SHB_OFF + 66)

// ---------------- scatter: smem-staged indices, 16 threads/edge ------------
__global__ void scatter_kernel(const float* __restrict__ x,
                               const int* __restrict__ pei, const int* __restrict__ nei,
                               float* __restrict__ sp, float* __restrict__ sn,
                               float* __restrict__ cp, float* __restrict__ cn, int E) {
    __shared__ int s_src[EB], s_dst[EB];
    const int* ei = blockIdx.y ? nei : pei;
    float* sum = blockIdx.y ? sn : sp;
    float* cnt = blockIdx.y ? cn : cp;
    long base = (long)blockIdx.x * EB;
    int tid = threadIdx.x;
    if (tid < EB) {
        long e = base + tid;
        s_src[tid] = (e < E) ? ei[e] : -1;
    } else {
        long e = base + (tid - EB);
        s_dst[tid - EB] = (e < E) ? ei[(long)E + e] : -1;
    }
    __syncthreads();
    int ch = tid & 15, eg = tid >> 4;
#pragma unroll
    for (int it = 0; it < EB / 16; ++it) {
        int e = it * 16 + eg;
        int dst = s_dst[e];
        if (dst < 0) continue;
        int src = s_src[e];
        float4 v = *reinterpret_cast<const float4*>(x + (size_t)src * FF + ch * 4);
        float* a = sum + (size_t)dst * FF + ch * 4;
        asm volatile("red.global.add.v4.f32 [%0], {%1,%2,%3,%4};"
                     :: "l"(a), "f"(v.x), "f"(v.y), "f"(v.z), "f"(v.w) : "memory");
        if (ch == 0)
            asm volatile("red.global.add.f32 [%0], %1;" :: "l"(cnt + dst), "f"(1.0f) : "memory");
    }
}

// ---------------- shared staging helpers ------------------------------------
// stage duplicated transposed weights: sWd[k*73 + (o>>3)*9 + (o&7)] = {W[o][k], W[o][k]}
__device__ __forceinline__ void stage_wdup(u64* sWd, const float* __restrict__ W, int tid) {
#pragma unroll
    for (int p = 0; p < 16; ++p) {
        int idx = p * 256 + tid;
        int o = idx >> 6, k = idx & 63;
        sWd[k * 73 + (o >> 3) * 9 + (o & 7)] = pack2(W[o * 64 + k]);
    }
}

// ---------------- K1: cc branch — GEMM on x + full x-side hyperbolic math --
// block: 256 nodes x branch by. thread: og=tid&7 outputs 8og..+7, ng=tid>>3,
// node pairs ng+32p (p=0..3) as f32x2 lanes.
__global__ void __launch_bounds__(256, 2)
cc_kernel(const float* __restrict__ x,
          const float* __restrict__ Wpc, const float* __restrict__ Wnc,
          const float* __restrict__ bpc, const float* __restrict__ bnc, int n) {
    extern __shared__ float sh[];
    float* sAx = sh;
    u64*   sWd = reinterpret_cast<u64*>(sh + SWD_OFF);
    float* sXN = sh + SN_OFF;
    float* sHB = sh + SHB_OFF;

    int by = blockIdx.y;
    const float* W = by ? Wnc : Wpc;
    const float* b = by ? bnc : bpc;
    long node0 = (long)blockIdx.x * 256;
    int tid = threadIdx.x;

    // warp 0: hyperbolic bias proj(expmap0(b))
    if (tid < 32) {
        float u0 = b[tid], u1 = b[tid + 32];
        float nb = fmaxf(sqrtf(wsum(u0 * u0 + u1 * u1)), 1e-15f);
        float s = tanhf(nb) / nb;
        float v0 = u0 * s, v1 = u1 * s;
        float vn = fmaxf(sqrtf(wsum(v0 * v0 + v1 * v1)), 1e-15f);
        if (vn > 0.996f) { float p = 0.996f / vn; v0 *= p; v1 *= p; }
        sHB[tid] = v0; sHB[tid + 32] = v1;
    }

    stage_wdup(sWd, W, tid);

    {   // stage x transposed: sAx[k*256 + node]
        int nl = tid & 63, kc = tid >> 6;
#pragma unroll
        for (int q = 0; q < 4; ++q) {
            int node = q * 64 + nl;
            long gn = node0 + node;
            bool ok = gn < n;
            const float4* row = reinterpret_cast<const float4*>(x + (size_t)(ok ? gn : 0) * 64);
#pragma unroll
            for (int pk = 0; pk < 4; ++pk) {
                int k4 = kc + 4 * pk;
                float4 v = ok ? row[k4] : make_float4(0.f, 0.f, 0.f, 0.f);
                sAx[(4 * k4 + 0) * 256 + node] = v.x;
                sAx[(4 * k4 + 1) * 256 + node] = v.y;
                sAx[(4 * k4 + 2) * 256 + node] = v.z;
                sAx[(4 * k4 + 3) * 256 + node] = v.w;
            }
        }
    }
    __syncthreads();
    {   // ||x|| per node column
        float acc = 0.f;
#pragma unroll
        for (int k = 0; k < 64; ++k) { float v = sAx[k * 256 + tid]; acc = fmaf(v, v, acc); }
        sXN[tid] = fmaxf(sqrtf(acc), 1e-15f);
    }
    __syncthreads();

    int og = tid & 7, ng = tid >> 3;
    u64 hbp2[8];
#pragma unroll
    for (int j = 0; j < 8; ++j) hbp2[j] = pack2(sHB[8 * og + j]);

    const u64* sA64 = reinterpret_cast<const u64*>(sAx);
    u64 acc[4][8];
#pragma unroll
    for (int p = 0; p < 4; ++p)
#pragma unroll
        for (int o = 0; o < 8; ++o) acc[p][o] = 0ull;

#pragma unroll 4
    for (int k = 0; k < 64; ++k) {
        u64 a[4];
#pragma unroll
        for (int p = 0; p < 4; ++p) a[p] = sA64[k * 128 + ng + 32 * p];
        const u64* wr = &sWd[k * 73 + og * 9];
        u64 w[8];
#pragma unroll
        for (int o = 0; o < 8; ++o) w[o] = wr[o];
#pragma unroll
        for (int p = 0; p < 4; ++p)
#pragma unroll
            for (int o = 0; o < 8; ++o) acc[p][o] = fma2(a[p], w[o], acc[p][o]);
    }

    // x-side epilogue: scC per node, store s = mvC*scC, meta = (x2, xy)
#pragma unroll
    for (int p = 0; p < 4; ++p) {
        u64 ss2 = 0ull, dh2 = 0ull;
#pragma unroll
        for (int o = 0; o < 8; ++o) {
            ss2 = fma2(acc[p][o], acc[p][o], ss2);
            dh2 = fma2(acc[p][o], hbp2[o], dh2);
        }
#pragma unroll
        for (int off = 1; off < 8; off <<= 1) {
            ss2 = add2(ss2, __shfl_xor_sync(0xffffffffu, ss2, off));
            dh2 = add2(dh2, __shfl_xor_sync(0xffffffffu, dh2, off));
        }
        float2 ss = unpack2(ss2), dh = unpack2(dh2);
        int pairL = ng + 32 * p;
        long pairG = node0 / 2 + pairL;
        if (2 * pairG >= n) continue;

        float xne = sXN[2 * pairL], xno = sXN[2 * pairL + 1];
        float mnCe = fmaxf(sqrtf(ss.x), 1e-15f);
        float tCe = tanhf(mnCe / xne * atanhf(fminf(xne, 1.0f - 1e-7f)));
        float sne = fminf(tCe, 0.996f);
        float scCe = sne / mnCe;
        float mnCo = fmaxf(sqrtf(ss.y), 1e-15f);
        float tCo = tanhf(mnCo / xno * atanhf(fminf(xno, 1.0f - 1e-7f)));
        float sno = fminf(tCo, 0.996f);
        float scCo = sno / mnCo;

        u64 sc2 = packlh(scCe, scCo);
        u64* dst = g_s + ((size_t)pairG * 2 + by) * 64 + 8 * og;
#pragma unroll
        for (int o = 0; o < 8; ++o) dst[o] = mul2(acc[p][o], sc2);
        if (og == 0) {
            g_meta[(size_t)(2 * pairG) * 2 + by]     = make_float2(sne * sne, scCe * dh.x);
            g_meta[(size_t)(2 * pairG + 1) * 2 + by] = make_float2(sno * sno, scCo * dh.y);
        }
    }
}

// ---------------- K3: agg branch — GEMM on means + final epilogue ----------
__global__ void __launch_bounds__(256, 2)
agg_kernel(const float* __restrict__ Wp, const float* __restrict__ Wn,
           const float* __restrict__ bpc, const float* __restrict__ bnc,
           float* __restrict__ out, int n) {
    extern __shared__ float sh[];
    float* sAa = sh;
    u64*   sWd = reinterpret_cast<u64*>(sh + SWD_OFF);
    float* sPN = sh + SN_OFF;
    float* sHB = sh + SHB_OFF;

    int by = blockIdx.y;
    const float* W = by ? Wn : Wp;
    const float* b = by ? bnc : bpc;
    const float* sums = by ? g_sum_neg : g_sum_pos;
    const float* cnts = by ? g_cnt_neg : g_cnt_pos;
    long node0 = (long)blockIdx.x * 256;
    int tid = threadIdx.x;

    if (tid < 32) {
        float u0 = b[tid], u1 = b[tid + 32];
        float nb = fmaxf(sqrtf(wsum(u0 * u0 + u1 * u1)), 1e-15f);
        float s = tanhf(nb) / nb;
        float v0 = u0 * s, v1 = u1 * s;
        float vn = fmaxf(sqrtf(wsum(v0 * v0 + v1 * v1)), 1e-15f);
        if (vn > 0.996f) { float p = 0.996f / vn; v0 *= p; v1 *= p; }
        sHB[tid] = v0; sHB[tid + 32] = v1;
        float y2v = wsum(v0 * v0 + v1 * v1);
        if (tid == 0) sHB[64] = y2v;
    }

    stage_wdup(sWd, W, tid);

    {   // stage mean vectors (scaled by 1/cnt)
        int nl = tid & 63, kc = tid >> 6;
#pragma unroll
        for (int q = 0; q < 4; ++q) {
            int node = q * 64 + nl;
            long gn = node0 + node;
            bool ok = gn < n;
            long gc = ok ? gn : 0;
            float scale = 1.0f / fmaxf(cnts[gc], 1.0f);
            const float4* row = reinterpret_cast<const float4*>(sums + (size_t)gc * 64);
#pragma unroll
            for (int pk = 0; pk < 4; ++pk) {
                int k4 = kc + 4 * pk;
                float4 v = ok ? row[k4] : make_float4(0.f, 0.f, 0.f, 0.f);
                sAa[(4 * k4 + 0) * 256 + node] = v.x * scale;
                sAa[(4 * k4 + 1) * 256 + node] = v.y * scale;
                sAa[(4 * k4 + 2) * 256 + node] = v.z * scale;
                sAa[(4 * k4 + 3) * 256 + node] = v.w * scale;
            }
        }
    }
    __syncthreads();
    {   // ||mean|| per node
        float acc = 0.f;
#pragma unroll
        for (int k = 0; k < 64; ++k) { float v = sAa[k * 256 + tid]; acc = fmaf(v, v, acc); }
        sPN[tid] = fmaxf(sqrtf(acc), 1e-15f);
    }
    __syncthreads();

    int og = tid & 7, ng = tid >> 3;
    float hbf[8];
#pragma unroll
    for (int j = 0; j < 8; ++j) hbf[j] = sHB[8 * og + j];
    float y2 = sHB[64];

    const u64* sA64 = reinterpret_cast<const u64*>(sAa);
    u64 acc[4][8];
#pragma unroll
    for (int p = 0; p < 4; ++p)
#pragma unroll
        for (int o = 0; o < 8; ++o) acc[p][o] = 0ull;

#pragma unroll 4
    for (int k = 0; k < 64; ++k) {
        u64 a[4];
#pragma unroll
        for (int p = 0; p < 4; ++p) a[p] = sA64[k * 128 + ng + 32 * p];
        const u64* wr = &sWd[k * 73 + og * 9];
        u64 w[8];
#pragma unroll
        for (int o = 0; o < 8; ++o) w[o] = wr[o];
#pragma unroll
        for (int p = 0; p < 4; ++p)
#pragma unroll
            for (int o = 0; o < 8; ++o) acc[p][o] = fma2(a[p], w[o], acc[p][o]);
    }

    // final epilogue: scP from agg norms; g1/g2 from precomputed meta; out
#pragma unroll
    for (int p = 0; p < 4; ++p) {
        u64 ss2 = 0ull;
#pragma unroll
        for (int o = 0; o < 8; ++o) ss2 = fma2(acc[p][o], acc[p][o], ss2);
#pragma unroll
        for (int off = 1; off < 8; off <<= 1)
            ss2 = add2(ss2, __shfl_xor_sync(0xffffffffu, ss2, off));
        float2 ss = unpack2(ss2);
        int pairL = ng + 32 * p;
        long pairG = node0 / 2 + pairL;
        if (2 * pairG >= n) continue;

        float pne = sPN[2 * pairL], pno = sPN[2 * pairL + 1];
        float mnPe = fmaxf(sqrtf(ss.x), 1e-15f);
        float scPe = fminf(tanhf(mnPe / pne * atanhf(fminf(pne, 1.0f - 1e-7f))), 0.996f) / mnPe;
        float mnPo = fmaxf(sqrtf(ss.y), 1e-15f);
        float scPo = fminf(tanhf(mnPo / pno * atanhf(fminf(pno, 1.0f - 1e-7f))), 0.996f) / mnPo;

        float2 me = g_meta[(size_t)(2 * pairG) * 2 + by];
        float2 mo = g_meta[(size_t)(2 * pairG + 1) * 2 + by];

        float g1e, g2e, g1o, g2o;
        {
            float x2 = me.x, xy = me.y;
            float f1 = 1.0f + 2.0f * xy + y2;
            float f2 = 1.0f - x2;
            float den = fmaxf(1.0f + 2.0f * xy + x2 * y2, 1e-15f);
            float inv = 1.0f / den;
            float qsq = fmaxf(f1 * f1 * x2 + 2.0f * f1 * f2 * xy + f2 * f2 * y2, 0.0f) * (inv * inv);
            float qn = fmaxf(sqrtf(qsq), 1e-15f);
            float clip = (qn > 0.996f) ? (0.996f / qn) : 1.0f;
            g1e = f1 * inv * clip; g2e = f2 * inv * clip;
        }
        {
            float x2 = mo.x, xy = mo.y;
            float f1 = 1.0f + 2.0f * xy + y2;
            float f2 = 1.0f - x2;
            float den = fmaxf(1.0f + 2.0f * xy + x2 * y2, 1e-15f);
            float inv = 1.0f / den;
            float qsq = fmaxf(f1 * f1 * x2 + 2.0f * f1 * f2 * xy + f2 * f2 * y2, 0.0f) * (inv * inv);
            float qn = fmaxf(sqrtf(qsq), 1e-15f);
            float clip = (qn > 0.996f) ? (0.996f / qn) : 1.0f;
            g1o = f1 * inv * clip; g2o = f2 * inv * clip;
        }

        const u64* sp = g_s + ((size_t)pairG * 2 + by) * 64 + 8 * og;
        float oe[8], oo[8];
#pragma unroll
        for (int o = 0; o < 8; ++o) {
            float2 mv = unpack2(acc[p][o]);
            float2 sv = unpack2(sp[o]);
            oe[o] = fmaf(mv.x, scPe, fmaf(g1e, sv.x, g2e * hbf[o]));
            oo[o] = fmaf(mv.y, scPo, fmaf(g1o, sv.y, g2o * hbf[o]));
        }
        long ge = node0 + 2 * pairL;
        float4* de = reinterpret_cast<float4*>(out + ge * 128 + by * 64 + 8 * og);
        de[0] = make_float4(oe[0], oe[1], oe[2], oe[3]);
        de[1] = make_float4(oe[4], oe[5], oe[6], oe[7]);
        float4* dq = reinterpret_cast<float4*>(out + (ge + 1) * 128 + by * 64 + 8 * og);
        dq[0] = make_float4(oo[0], oo[1], oo[2], oo[3]);
        dq[1] = make_float4(oo[4], oo[5], oo[6], oo[7]);
    }
}

// ---------------------------------------------------------------------------
extern "C" void kernel_launch(void* const* d_in, const int* in_sizes, int n_in,
                              void* d_out, int out_size) {
    const float* x   = (const float*)d_in[0];
    const float* Wp  = (const float*)d_in[1];
    const float* Wpc = (const float*)d_in[2];
    const float* bpc = (const float*)d_in[3];
    const float* Wn  = (const float*)d_in[4];
    const float* Wnc = (const float*)d_in[5];
    const float* bnc = (const float*)d_in[6];
    const int* pei   = (const int*)d_in[7];
    const int* nei   = (const int*)d_in[8];
    float* out = (float*)d_out;

    int n = in_sizes[0] / 64;
    int E = in_sizes[7] / 2;

    void *psum_p, *psum_n, *pcnt_p, *pcnt_n;
    cudaGetSymbolAddress(&psum_p, g_sum_pos);
    cudaGetSymbolAddress(&psum_n, g_sum_neg);
    cudaGetSymbolAddress(&pcnt_p, g_cnt_pos);
    cudaGetSymbolAddress(&pcnt_n, g_cnt_neg);
    cudaMemsetAsync(psum_p, 0, (size_t)n * 64 * sizeof(float));
    cudaMemsetAsync(psum_n, 0, (size_t)n * 64 * sizeof(float));
    cudaMemsetAsync(pcnt_p, 0, (size_t)n * sizeof(float));
    cudaMemsetAsync(pcnt_n, 0, (size_t)n * sizeof(float));

    const int FSMEM = FSMEM_FLOATS * (int)sizeof(float);   // 104,200 B
    cudaFuncSetAttribute(cc_kernel, cudaFuncAttributeMaxDynamicSharedMemorySize, FSMEM);
    cudaFuncSetAttribute(agg_kernel, cudaFuncAttributeMaxDynamicSharedMemorySize, FSMEM);

    dim3 ggrid((n + 255) / 256, 2);
    cc_kernel<<<ggrid, 256, FSMEM>>>(x, Wpc, Wnc, bpc, bnc, n);

    dim3 sgrid((E + EB - 1) / EB, 2);
    scatter_kernel<<<sgrid, 256>>>(x, pei, nei,
                                   (float*)psum_p, (float*)psum_n,
                                   (float*)pcnt_p, (float*)pcnt_n, E);

    agg_kernel<<<ggrid, 256, FSMEM>>>(Wp, Wn, bpc, bnc, out, n);
}

// round 15
// speedup vs baseline: 1.2575x; 1.0659x over previous
#include <cuda_runtime.h>
#include <cstdint>

#define NN 100096
#define FF 64
#define EE 1664000
#define SCAN_BS 512

// ---------------- scratch (device globals: no runtime allocation) ----------
__device__ float g_mean_pos[(size_t)NN * FF];
__device__ float g_mean_neg[(size_t)NN * FF];
__device__ int   g_deg_pos[NN];
__device__ int   g_deg_neg[NN];
__device__ int   g_off_pos[NN];
__device__ int   g_off_neg[NN];
__device__ int   g_cur_pos[NN];
__device__ int   g_cur_neg[NN];
__device__ int   g_idx_pos[EE];
__device__ int   g_idx_neg[EE];
__device__ int   g_bsum[2 * 256];
__device__ int   g_boff[2 * 256];
__device__ float g_mv[(size_t)NN * 256];   // matvec results: [node][Pp|Pc|Np|Nc]
__device__ float g_mvn[(size_t)NN * 4];    // matvec norms (clipped)
__device__ float g_hb[136];                // hb_pos, hb_neg, y2_pos, y2_neg
__device__ float g_xn[NN];
__device__ float g_pn[NN];
__device__ float g_nn[NN];

__device__ __forceinline__ float wsum(float v) {
#pragma unroll
    for (int o = 16; o > 0; o >>= 1) v += __shfl_xor_sync(0xffffffffu, v, o);
    return v;
}

// packed f32x2 helpers (sm_103a)
__device__ __forceinline__ unsigned long long fma2(unsigned long long a,
                                                   unsigned long long b,
                                                   unsigned long long c) {
    unsigned long long d;
    asm("fma.rn.f32x2 %0, %1, %2, %3;" : "=l"(d) : "l"(a), "l"(b), "l"(c));
    return d;
}
__device__ __forceinline__ unsigned long long pack2(float v) {
    unsigned long long d;
    asm("mov.b64 %0, {%1, %1};" : "=l"(d) : "r"(__float_as_uint(v)));
    return d;
}
__device__ __forceinline__ float2 unpack2(unsigned long long a) {
    unsigned int lo, hi;
    asm("mov.b64 {%0, %1}, %2;" : "=r"(lo), "=r"(hi) : "l"(a));
    return make_float2(__uint_as_float(lo), __uint_as_float(hi));
}

// ---------------- CSR build step 1: degree histogram (+ bias in block 0) ---
__global__ void hist_kernel(const int* __restrict__ pei, const int* __restrict__ nei,
                            const float* __restrict__ bpc, const float* __restrict__ bnc,
                            int E) {
    int list = blockIdx.y;
    const int* ei = list ? nei : pei;
    int* deg = list ? g_deg_neg : g_deg_pos;
    long e = (long)blockIdx.x * 256 + threadIdx.x;
    if (e < E) atomicAdd(&deg[ei[(long)E + e]], 1);

    // fold the hyperbolic bias precompute into one warp of one block
    if (list == 0 && blockIdx.x == 0 && threadIdx.x < 32) {
        int lane = threadIdx.x;
        const float* bs[2] = {bpc, bnc};
#pragma unroll
        for (int i = 0; i < 2; ++i) {
            float u0 = bs[i][lane], u1 = bs[i][lane + 32];
            float nb = fmaxf(sqrtf(wsum(u0 * u0 + u1 * u1)), 1e-15f);
            float s = tanhf(nb) / nb;
            float v0 = u0 * s, v1 = u1 * s;
            float vn = fmaxf(sqrtf(wsum(v0 * v0 + v1 * v1)), 1e-15f);
            if (vn > 0.996f) { float p = 0.996f / vn; v0 *= p; v1 *= p; }
            g_hb[i * 64 + lane]      = v0;
            g_hb[i * 64 + 32 + lane] = v1;
            float y2 = wsum(v0 * v0 + v1 * v1);
            if (lane == 0) g_hb[128 + i] = y2;
        }
    }
}

// ---------------- CSR step 2a: per-block sums of degrees --------------------
__global__ void scan1_kernel(int n) {
    int list = blockIdx.y;
    const int* deg = list ? g_deg_neg : g_deg_pos;
    int i = blockIdx.x * SCAN_BS + threadIdx.x;
    int v = (i < n) ? deg[i] : 0;
#pragma unroll
    for (int o = 16; o > 0; o >>= 1) v += __shfl_xor_sync(0xffffffffu, v, o);
    __shared__ int ws[SCAN_BS / 32];
    int lane = threadIdx.x & 31, wid = threadIdx.x >> 5;
    if (lane == 0) ws[wid] = v;
    __syncthreads();
    if (threadIdx.x == 0) {
        int t = 0;
#pragma unroll
        for (int w = 0; w < SCAN_BS / 32; ++w) t += ws[w];
        g_bsum[list * 256 + blockIdx.x] = t;
    }
}

// ---------------- CSR step 2b: scan block sums (1 block, both lists) -------
__global__ void scan2_kernel(int NB) {
    __shared__ int s[256];
    int tid = threadIdx.x;
#pragma unroll
    for (int list = 0; list < 2; ++list) {
        int v = (tid < NB) ? g_bsum[list * 256 + tid] : 0;
        s[tid] = v;
        __syncthreads();
        for (int o = 1; o < 256; o <<= 1) {
            int t = (tid >= o) ? s[tid - o] : 0;
            __syncthreads();
            s[tid] += t;
            __syncthreads();
        }
        g_boff[list * 256 + tid] = s[tid] - v;   // exclusive
        __syncthreads();
    }
}

// ---------------- CSR step 2c: per-element offsets + cursors ---------------
__global__ void scan3_kernel(int n) {
    int list = blockIdx.y;
    const int* deg = list ? g_deg_neg : g_deg_pos;
    int* off = list ? g_off_neg : g_off_pos;
    int* cur = list ? g_cur_neg : g_cur_pos;
    int i = blockIdx.x * SCAN_BS + threadIdx.x;
    int lane = threadIdx.x & 31, wid = threadIdx.x >> 5;
    int v = (i < n) ? deg[i] : 0;
    int inc = v;
#pragma unroll
    for (int o = 1; o < 32; o <<= 1) {
        int t = __shfl_up_sync(0xffffffffu, inc, o);
        if (lane >= o) inc += t;
    }
    __shared__ int ws[SCAN_BS / 32];
    if (lane == 31) ws[wid] = inc;
    __syncthreads();
    if (wid == 0) {
        int wv = (lane < SCAN_BS / 32) ? ws[lane] : 0;
#pragma unroll
        for (int o = 1; o < SCAN_BS / 32; o <<= 1) {
            int t = __shfl_up_sync(0xffffffffu, wv, o);
            if (lane >= o) wv += t;
        }
        if (lane < SCAN_BS / 32) ws[lane] = wv;   // inclusive warp sums
    }
    __syncthreads();
    int base = g_boff[list * 256 + blockIdx.x] + (wid > 0 ? ws[wid - 1] : 0);
    int excl = base + inc - v;
    if (i < n) { off[i] = excl; cur[i] = excl; }
}

// ---------------- CSR step 3: fill src-index lists --------------------------
__global__ void fill_kernel(const int* __restrict__ pei, const int* __restrict__ nei, int E) {
    int list = blockIdx.y;
    const int* ei = list ? nei : pei;
    int* cur = list ? g_cur_neg : g_cur_pos;
    int* idx = list ? g_idx_neg : g_idx_pos;
    long e = (long)blockIdx.x * 256 + threadIdx.x;
    if (e >= E) return;
    int src = ei[e];
    int dst = ei[(long)E + e];
    int pos = atomicAdd(&cur[dst], 1);
    idx[pos] = src;
}

// ---------------- CSR step 4: warp-per-node gather-reduce -> mean -----------
__global__ void gather_kernel(const float* __restrict__ x, int n) {
    int list = blockIdx.y;
    const int* degA = list ? g_deg_neg : g_deg_pos;
    const int* offA = list ? g_off_neg : g_off_pos;
    const int* idx  = list ? g_idx_neg : g_idx_pos;
    float* mean = list ? g_mean_neg : g_mean_pos;
    int lane = threadIdx.x & 31, w = threadIdx.x >> 5;
    long node = (long)blockIdx.x * 8 + w;
    if (node >= n) return;
    int deg = degA[node], off = offA[node];

    float2 a0 = {0.f, 0.f}, a1 = {0.f, 0.f}, a2 = {0.f, 0.f}, a3 = {0.f, 0.f};
    for (int j0 = 0; j0 < deg; j0 += 32) {
        int m = min(32, deg - j0);
        int my = (lane < m) ? idx[off + j0 + lane] : 0;
        int t = 0;
        for (; t + 4 <= m; t += 4) {
            int s0 = __shfl_sync(0xffffffffu, my, t);
            int s1 = __shfl_sync(0xffffffffu, my, t + 1);
            int s2 = __shfl_sync(0xffffffffu, my, t + 2);
            int s3 = __shfl_sync(0xffffffffu, my, t + 3);
            float2 v0 = *reinterpret_cast<const float2*>(x + (size_t)s0 * FF + 2 * lane);
            float2 v1 = *reinterpret_cast<const float2*>(x + (size_t)s1 * FF + 2 * lane);
            float2 v2 = *reinterpret_cast<const float2*>(x + (size_t)s2 * FF + 2 * lane);
            float2 v3 = *reinterpret_cast<const float2*>(x + (size_t)s3 * FF + 2 * lane);
            a0.x += v0.x; a0.y += v0.y;
            a1.x += v1.x; a1.y += v1.y;
            a2.x += v2.x; a2.y += v2.y;
            a3.x += v3.x; a3.y += v3.y;
        }
        for (; t < m; ++t) {
            int s = __shfl_sync(0xffffffffu, my, t);
            float2 v = *reinterpret_cast<const float2*>(x + (size_t)s * FF + 2 * lane);
            a0.x += v.x; a0.y += v.y;
        }
    }
    float sx = (a0.x + a1.x) + (a2.x + a3.x);
    float sy = (a0.y + a1.y) + (a2.y + a3.y);
    float inv = 1.0f / (float)max(deg, 1);
    *reinterpret_cast<float2*>(mean + (size_t)node * FF + 2 * lane) =
        make_float2(sx * inv, sy * inv);
}

// ---------------- unified GEMM: all four matrices, plus norms --------------
// block: 256 nodes x matrix m = blockIdx.y
// thread: og=tid&7 (8 outputs as 4 f32x2), ng=tid>>3 (8 nodes)
__global__ void __launch_bounds__(256, 2)
gemm_kernel(const float* __restrict__ x,
            const float* __restrict__ Wp,  const float* __restrict__ Wpc,
            const float* __restrict__ Wn,  const float* __restrict__ Wnc,
            float* __restrict__ mv, int n) {
    extern __shared__ float sh[];
    float* sA = sh;              // [64][256] transposed node vectors
    float* sW = sh + 64 * 256;   // [64][68]  transposed weights

    int m = blockIdx.y;
    const float* W = (m == 0) ? Wp : (m == 1) ? Wpc : (m == 2) ? Wn : Wnc;
    const float* srcv = (m & 1) ? x : ((m == 0) ? g_mean_pos : g_mean_neg);
    long node0 = (long)blockIdx.x * 256;
    int tid = threadIdx.x;

    // stage W transposed: sW[k*68+o] = W[o*64+k]
#pragma unroll
    for (int p = 0; p < 16; ++p) {
        int idx = p * 256 + tid;
        int o = idx >> 6, k = idx & 63;
        sW[k * 68 + o] = W[o * 64 + k];
    }
    // stage A transposed (means already divided)
    {
        int nl = tid & 63, kc = tid >> 6;
#pragma unroll
        for (int q = 0; q < 4; ++q) {
            int node = q * 64 + nl;
            long gn = node0 + node;
            bool ok = gn < n;
            const float4* row = reinterpret_cast<const float4*>(srcv + (size_t)(ok ? gn : 0) * 64);
#pragma unroll
            for (int pk = 0; pk < 4; ++pk) {
                int k4 = kc + 4 * pk;
                float4 v = ok ? row[k4] : make_float4(0.f, 0.f, 0.f, 0.f);
                sA[(4 * k4 + 0) * 256 + node] = v.x;
                sA[(4 * k4 + 1) * 256 + node] = v.y;
                sA[(4 * k4 + 2) * 256 + node] = v.z;
                sA[(4 * k4 + 3) * 256 + node] = v.w;
            }
        }
    }
    __syncthreads();

    // input norms (m=0 -> pn, m=1 -> xn, m=2 -> nn), node `tid` column
    if (m < 3) {
        float acc = 0.f;
#pragma unroll
        for (int k = 0; k < 64; ++k) { float v = sA[k * 256 + tid]; acc = fmaf(v, v, acc); }
        long gn = node0 + tid;
        if (gn < n) {
            float* dst = (m == 0) ? g_pn : (m == 1) ? g_xn : g_nn;
            dst[gn] = fmaxf(sqrtf(acc), 1e-15f);
        }
    }

    int og = tid & 7, ng = tid >> 3;
    unsigned long long acc[8][4];
#pragma unroll
    for (int i = 0; i < 8; ++i)
#pragma unroll
        for (int j = 0; j < 4; ++j) acc[i][j] = 0ull;

#pragma unroll 4
    for (int k = 0; k < 64; ++k) {
        float4 a0 = *reinterpret_cast<const float4*>(&sA[k * 256 + 4 * ng]);
        float4 a1 = *reinterpret_cast<const float4*>(&sA[k * 256 + 128 + 4 * ng]);
        ulonglong2 w0 = *reinterpret_cast<const ulonglong2*>(&sW[k * 68 + 8 * og]);
        ulonglong2 w1 = *reinterpret_cast<const ulonglong2*>(&sW[k * 68 + 8 * og + 4]);
        unsigned long long wv0 = w0.x, wv1 = w0.y, wv2 = w1.x, wv3 = w1.y;
        float av[8] = {a0.x, a0.y, a0.z, a0.w, a1.x, a1.y, a1.z, a1.w};
#pragma unroll
        for (int i = 0; i < 8; ++i) {
            unsigned long long p2 = pack2(av[i]);
            acc[i][0] = fma2(p2, wv0, acc[i][0]);
            acc[i][1] = fma2(p2, wv1, acc[i][1]);
            acc[i][2] = fma2(p2, wv2, acc[i][2]);
            acc[i][3] = fma2(p2, wv3, acc[i][3]);
        }
    }

#pragma unroll
    for (int i = 0; i < 8; ++i) {
        int node = (i < 4) ? (4 * ng + i) : (128 + 4 * ng + (i - 4));
        long gn = node0 + node;
        float ss = 0.f;
#pragma unroll
        for (int j = 0; j < 4; ++j) {
            float2 v = unpack2(acc[i][j]);
            ss = fmaf(v.x, v.x, fmaf(v.y, v.y, ss));
        }
#pragma unroll
        for (int o = 4; o > 0; o >>= 1) ss += __shfl_xor_sync(0xffffffffu, ss, o);
        if (gn < n) {
            ulonglong2* dst = reinterpret_cast<ulonglong2*>(mv + gn * 256 + m * 64 + 8 * og);
            dst[0] = make_ulonglong2(acc[i][0], acc[i][1]);
            dst[1] = make_ulonglong2(acc[i][2], acc[i][3]);
            if (og == 0) g_mvn[gn * 4 + m] = fmaxf(sqrtf(ss), 1e-15f);
        }
    }
}

// ---------------- hyperbolic epilogue (warp per node) ----------------------
__device__ __forceinline__ void node_out3(
    float aP0, float aP1, float mnP, float pn,
    float aC0, float aC1, float mnC, float xn,
    float hb0, float hb1, float y2,
    float& o0, float& o1) {
    float tP = tanhf(mnP / pn * atanhf(fminf(pn, 1.0f - 1e-7f)));
    float scP = fminf(tP, 0.996f) / mnP;
    float r0 = aP0 * scP, r1 = aP1 * scP;

    float tC = tanhf(mnC / xn * atanhf(fminf(xn, 1.0f - 1e-7f)));
    float sn_ = fminf(tC, 0.996f);
    float scC = sn_ / mnC;
    float s0 = aC0 * scC, s1 = aC1 * scC;

    float x2 = sn_ * sn_;
    float xy = wsum(s0 * hb0 + s1 * hb1);
    float f1 = 1.0f + 2.0f * xy + y2;
    float f2 = 1.0f - x2;
    float den = fmaxf(1.0f + 2.0f * xy + x2 * y2, 1e-15f);
    float inv = 1.0f / den;
    float q0 = (f1 * s0 + f2 * hb0) * inv;
    float q1 = (f1 * s1 + f2 * hb1) * inv;
    float qsq = fmaxf(f1 * f1 * x2 + 2.0f * f1 * f2 * xy + f2 * f2 * y2, 0.0f) * (inv * inv);
    float qn = fmaxf(sqrtf(qsq), 1e-15f);
    if (qn > 0.996f) { float p = 0.996f / qn; q0 *= p; q1 *= p; }
    o0 = r0 + q0; o1 = r1 + q1;
}

__global__ void epilogue_kernel(float* __restrict__ out, int n) {
    long w = (long)(blockIdx.x * blockDim.x + threadIdx.x) >> 5;
    int lane = threadIdx.x & 31;
    if (w >= n) return;

    const float* row = g_mv + (size_t)w * 256;
    float Pp0 = row[lane],       Pp1 = row[32 + lane];
    float Pc0 = row[64 + lane],  Pc1 = row[96 + lane];
    float Np0 = row[128 + lane], Np1 = row[160 + lane];
    float Nc0 = row[192 + lane], Nc1 = row[224 + lane];

    float4 mn = *reinterpret_cast<const float4*>(g_mvn + (size_t)w * 4);
    float xn = g_xn[w], pn = g_pn[w], nn = g_nn[w];
    float hbp0 = g_hb[lane],      hbp1 = g_hb[32 + lane];
    float hbn0 = g_hb[64 + lane], hbn1 = g_hb[96 + lane];
    float y2p = g_hb[128], y2n = g_hb[129];

    float oP0, oP1, oN0, oN1;
    node_out3(Pp0, Pp1, mn.x, pn, Pc0, Pc1, mn.y, xn, hbp0, hbp1, y2p, oP0, oP1);
    node_out3(Np0, Np1, mn.z, nn, Nc0, Nc1, mn.w, xn, hbn0, hbn1, y2n, oN0, oN1);

    out[w * 128 + lane]      = oP0;
    out[w * 128 + 32 + lane] = oP1;
    out[w * 128 + 64 + lane] = oN0;
    out[w * 128 + 96 + lane] = oN1;
}

// ---------------------------------------------------------------------------
extern "C" void kernel_launch(void* const* d_in, const int* in_sizes, int n_in,
                              void* d_out, int out_size) {
    const float* x   = (const float*)d_in[0];
    const float* Wp  = (const float*)d_in[1];
    const float* Wpc = (const float*)d_in[2];
    const float* bpc = (const float*)d_in[3];
    const float* Wn  = (const float*)d_in[4];
    const float* Wnc = (const float*)d_in[5];
    const float* bnc = (const float*)d_in[6];
    const int* pei   = (const int*)d_in[7];
    const int* nei   = (const int*)d_in[8];
    float* out = (float*)d_out;

    int n = in_sizes[0] / 64;
    int E = in_sizes[7] / 2;
    if (E > EE) E = EE;

    void *pdeg_p, *pdeg_n, *pmv;
    cudaGetSymbolAddress(&pdeg_p, g_deg_pos);
    cudaGetSymbolAddress(&pdeg_n, g_deg_neg);
    cudaGetSymbolAddress(&pmv, g_mv);
    cudaMemsetAsync(pdeg_p, 0, (size_t)n * sizeof(int));
    cudaMemsetAsync(pdeg_n, 0, (size_t)n * sizeof(int));

    int NB = (n + SCAN_BS - 1) / SCAN_BS;   // <= 256

    dim3 egrid((E + 255) / 256, 2);
    hist_kernel<<<egrid, 256>>>(pei, nei, bpc, bnc, E);
    scan1_kernel<<<dim3(NB, 2), SCAN_BS>>>(n);
    scan2_kernel<<<1, 256>>>(NB);
    scan3_kernel<<<dim3(NB, 2), SCAN_BS>>>(n);
    fill_kernel<<<egrid, 256>>>(pei, nei, E);
    gather_kernel<<<dim3((n + 7) / 8, 2), 256>>>(x, n);

    const int GSMEM = (64 * 256 + 64 * 68) * (int)sizeof(float); // 82,944 B
    cudaFuncSetAttribute(gemm_kernel, cudaFuncAttributeMaxDynamicSharedMemorySize, GSMEM);
    dim3 ggrid((n + 255) / 256, 4);
    gemm_kernel<<<ggrid, 256, GSMEM>>>(x, Wp, Wpc, Wn, Wnc, (float*)pmv, n);

    int eblocks = (int)(((long)n * 32 + 255) / 256);
    epilogue_kernel<<<eblocks, 256>>>(out, n);
}